// round 14
// baseline (speedup 1.0000x reference)
#include <cuda_runtime.h>
#include <cstdint>

#define Bb 16
#define Nn 512
#define Tt 24
#define Dd 64
#define Ee 64
#define Hh 64

typedef unsigned long long ull;
typedef unsigned int u32;

// bf16 hi/lo operand planes, row-major 64x64 tiles (128B rows): [(b*Tt+t)*8 + jt]
__device__ __align__(128) unsigned char g_e2h[(size_t)Bb * Tt * Nn * 128];
__device__ __align__(128) unsigned char g_e2l[(size_t)Bb * Tt * Nn * 128];
__device__ __align__(128) unsigned char g_xth[(size_t)Bb * Tt * Dd * 1024];
__device__ __align__(128) unsigned char g_xtl[(size_t)Bb * Tt * Dd * 1024];

// ---------- SIMT helpers ----------
__device__ __forceinline__ ull dup2(float a) {
    ull r; asm("mov.b64 %0, {%1, %1};" : "=l"(r) : "f"(a)); return r;
}
__device__ __forceinline__ void fma2(ull& c, ull a, ull b) {
    asm("fma.rn.f32x2 %0, %1, %2, %0;" : "+l"(c) : "l"(a), "l"(b));
}
__device__ __forceinline__ float2 unpk(ull v) {
    float2 r; asm("mov.b64 {%0, %1}, %2;" : "=f"(r.x), "=f"(r.y) : "l"(v)); return r;
}
__device__ __forceinline__ void cp16(void* s, const void* g) {
    u32 sa = (u32)__cvta_generic_to_shared(s);
    asm volatile("cp.async.cg.shared.global [%0], [%1], 16;" ::"r"(sa), "l"(g));
}
__device__ __forceinline__ void cp16s(u32 sa, const void* g) {
    asm volatile("cp.async.cg.shared.global [%0], [%1], 16;" ::"r"(sa), "l"(g));
}
__device__ __forceinline__ void cp_commit() { asm volatile("cp.async.commit_group;"); }
template <int N> __device__ __forceinline__ void cp_wait() {
    asm volatile("cp.async.wait_group %0;" ::"n"(N));
}
// split (v0,v1) -> bf16x2 hi (v0 in low half) + bf16x2 lo residual
__device__ __forceinline__ void split2(float v0, float v1, u32& h, u32& l) {
    u32 hp;
    asm("cvt.rn.satfinite.bf16x2.f32 %0, %1, %2;" : "=r"(hp) : "f"(v1), "f"(v0));
    float h0 = __uint_as_float(hp << 16);
    float h1 = __uint_as_float(hp & 0xffff0000u);
    float l0 = v0 - h0, l1 = v1 - h1;
    asm("cvt.rn.satfinite.bf16x2.f32 %0, %1, %2;" : "=r"(l) : "f"(l1), "f"(l0));
    h = hp;
}

// ---------- tensor-core (warp mma) helpers ----------
__device__ __forceinline__ void ldm4(u32 addr, u32& r0, u32& r1, u32& r2, u32& r3) {
    asm volatile("ldmatrix.sync.aligned.m8n8.x4.shared.b16 {%0,%1,%2,%3}, [%4];"
                 : "=r"(r0), "=r"(r1), "=r"(r2), "=r"(r3) : "r"(addr));
}
__device__ __forceinline__ void mmab(float* d, const u32* a, u32 b0, u32 b1) {
    asm volatile(
        "mma.sync.aligned.m16n8k16.row.col.f32.bf16.bf16.f32 "
        "{%0,%1,%2,%3},{%4,%5,%6,%7},{%8,%9},{%0,%1,%2,%3};"
        : "+f"(d[0]), "+f"(d[1]), "+f"(d[2]), "+f"(d[3])
        : "r"(a[0]), "r"(a[1]), "r"(a[2]), "r"(a[3]), "r"(b0), "r"(b1));
}
// copy 8KB gmem plane (64 rows x 128B) into smem rows of stride 144B
__device__ __forceinline__ void cp_tile(u32 dst, const unsigned char* src, int tid) {
#pragma unroll
    for (int i = 0; i < 4; i++) {
        int ch = tid + 128 * i;  // 0..511
        u32 row = (u32)(ch >> 3), c16 = (u32)(ch & 7);
        cp16s(dst + row * 144 + c16 * 16, src + (size_t)ch * 16);
    }
}

// One K-chunk (k=16) of a 3-term split GEMM over 8 accumulators.
__device__ __forceinline__ void gemm_kc(float (*D)[4], const u32* Ah, const u32* Al,
                                        u32 bbase, u32 brl, u32 bq, int kc) {
    u32 Bh[4][4], Bl[4][4];
#pragma unroll
    for (int nbp = 0; nbp < 4; nbp++) {
        u32 ro = ((u32)(2 * nbp) + bq) * 1152 + brl + (u32)kc * 32;
        ldm4(bbase + ro, Bh[nbp][0], Bh[nbp][1], Bh[nbp][2], Bh[nbp][3]);
        ldm4(bbase + 9216 + ro, Bl[nbp][0], Bl[nbp][1], Bl[nbp][2], Bl[nbp][3]);
    }
#pragma unroll
    for (int nbp = 0; nbp < 4; nbp++) {
        mmab(D[2 * nbp], Ah, Bh[nbp][0], Bh[nbp][1]);
        mmab(D[2 * nbp + 1], Ah, Bh[nbp][2], Bh[nbp][3]);
    }
#pragma unroll
    for (int nbp = 0; nbp < 4; nbp++) {
        mmab(D[2 * nbp], Al, Bh[nbp][0], Bh[nbp][1]);
        mmab(D[2 * nbp + 1], Al, Bh[nbp][2], Bh[nbp][3]);
    }
#pragma unroll
    for (int nbp = 0; nbp < 4; nbp++) {
        mmab(D[2 * nbp], Ah, Bl[nbp][0], Bl[nbp][1]);
        mmab(D[2 * nbp + 1], Ah, Bl[nbp][2], Bl[nbp][3]);
    }
}

// ============================================================================
// Kernel P: E2 = x@W2+b2 -> bf16 hi/lo tiles [j][e]; X^T tiles [d][j] hi/lo.
// grid = B*T*8 (j-tile 64), 128 threads.
// ============================================================================
__global__ void __launch_bounds__(128, 4)
gcn_proj(const float* __restrict__ x, const float* __restrict__ W2,
         const float* __restrict__ b2) {
    extern __shared__ float sm[];
    float* xb = sm;          // [64][68]
    float* Ws = sm + 4352;   // [64][64]
    float* bs = sm + 8448;   // 64

    const int tid = threadIdx.x;
    const int blk = blockIdx.x;
    const int nt = blk & 7, bt = blk >> 3;
    const int t = bt % Tt, b = bt / Tt;
    const int n0 = nt * 64;
    const float* xg = x + ((size_t)(b * Nn + n0) * Tt + t) * Dd;
    const size_t tile = (size_t)(b * Tt + t) * 8 + nt;

#pragma unroll
    for (int i = 0; i < 8; i++) {
        int ch = tid + 128 * i, row = ch >> 4, c16 = ch & 15;
        cp16(&xb[row * 68 + c16 * 4], &xg[(size_t)row * (Tt * Dd) + c16 * 4]);
        cp16(&Ws[ch * 4], &W2[ch * 4]);
    }
    if (tid < 16) cp16(&bs[tid * 4], &b2[tid * 4]);
    cp_commit();
    cp_wait<0>();
    __syncthreads();

    const int r0 = (tid >> 4) * 8, c0 = (tid & 15) * 4;
    ull acc[8][2];
    {
        ulonglong2 bb = *(const ulonglong2*)&bs[c0];
#pragma unroll
        for (int u = 0; u < 8; u++) { acc[u][0] = bb.x; acc[u][1] = bb.y; }
    }
#pragma unroll 8
    for (int d = 0; d < 64; d++) {
        ulonglong2 wv = *(const ulonglong2*)&Ws[d * 64 + c0];
#pragma unroll
        for (int u = 0; u < 8; u++) {
            ull ad = dup2(xb[(r0 + u) * 68 + d]);
            fma2(acc[u][0], ad, wv.x);
            fma2(acc[u][1], ad, wv.y);
        }
    }
    unsigned char* e2h = g_e2h + tile * 8192;
    unsigned char* e2l = g_e2l + tile * 8192;
#pragma unroll
    for (int u = 0; u < 8; u++) {
        float2 p0 = unpk(acc[u][0]), p1 = unpk(acc[u][1]);
        u32 h0, l0, h1, l1;
        split2(p0.x, p0.y, h0, l0);
        split2(p1.x, p1.y, h1, l1);
        u32 off = (u32)(r0 + u) * 128 + (u32)c0 * 2;
        *(uint2*)(e2h + off) = make_uint2(h0, h1);
        *(uint2*)(e2l + off) = make_uint2(l0, l1);
    }
    {
        const int dd = tid >> 1, jh = (tid & 1) * 32;
        u32 hi[16], lo[16];
#pragma unroll
        for (int c = 0; c < 16; c++) {
            float v0 = xb[(jh + 2 * c) * 68 + dd];
            float v1 = xb[(jh + 2 * c + 1) * 68 + dd];
            split2(v0, v1, hi[c], lo[c]);
        }
        unsigned char* xth = g_xth + tile * 8192;
        unsigned char* xtl = g_xtl + tile * 8192;
        u32 base = (u32)dd * 128 + (u32)jh * 2;
#pragma unroll
        for (int c4 = 0; c4 < 4; c4++) {
            *(uint4*)(xth + base + 16 * c4) = *(uint4*)&hi[4 * c4];
            *(uint4*)(xtl + base + 16 * c4) = *(uint4*)&lo[4 * c4];
        }
    }
}

// ============================================================================
// Kernel M: mma.sync main, GEMM1 pipelined one j-tile ahead.
// grid = B*T*8 (i-tile 64), 128 threads, 2 CTAs/SM.
// ============================================================================
__global__ void __launch_bounds__(128, 2)
gcn_main(const float* __restrict__ x, const float* __restrict__ W1,
         const float* __restrict__ b1, const float* __restrict__ W,
         const float* __restrict__ bias, float* __restrict__ out) {
    extern __shared__ unsigned char SB[];
    const u32 sb = (u32)__cvta_generic_to_shared(SB);
    const u32 E1H = 0, E1L = 9216, E2B = 18432, XTB = 55296;
    const u32 BS1 = 92160, BSO = 92416;

    const int tid = threadIdx.x, w = tid >> 5, l = tid & 31;
    const int blk = blockIdx.x;
    const int it = blk & 7, bt = blk >> 3;
    const int t = bt % Tt, b = bt / Tt;
    const int i0 = it * 64;
    const size_t tb = (size_t)(b * Tt + t) * 8;
    const float* xg = x + ((size_t)b * Nn * Tt + t) * Dd;

    // ---- g0: x_i fp32 -> E2 buf0, W1 fp32 -> E2 buf1, biases ----
    {
        float* xi = (float*)(SB + E2B);
        float* W1s = (float*)(SB + E2B + 18432);
#pragma unroll
        for (int i = 0; i < 8; i++) {
            int ch = tid + 128 * i, row = ch >> 4, c16 = ch & 15;
            cp16(&xi[row * 64 + c16 * 4], &xg[(size_t)(i0 + row) * (Tt * Dd) + c16 * 4]);
            cp16(&W1s[ch * 4], &W1[ch * 4]);
        }
        if (tid < 16) cp16((float*)(SB + BS1) + tid * 4, b1 + tid * 4);
        else if (tid < 32) cp16((float*)(SB + BSO) + (tid - 16) * 4, bias + (tid - 16) * 4);
        cp_commit();
    }
    cp_tile(sb + XTB, g_xth + tb * 8192, tid);
    cp_tile(sb + XTB + 9216, g_xtl + tb * 8192, tid);
    cp_commit();
    cp_tile(sb + XTB + 18432, g_xth + (tb + 1) * 8192, tid);
    cp_tile(sb + XTB + 18432 + 9216, g_xtl + (tb + 1) * 8192, tid);
    cp_commit();
    cp_wait<2>();
    __syncthreads();

    // ---- GEMM0 (SIMT): E1 = x_i @ W1 + b1 -> bf16 planes stride 144 ----
    {
        const float* xi = (const float*)(SB + E2B);
        const float* W1s = (const float*)(SB + E2B + 18432);
        const float* bs1 = (const float*)(SB + BS1);
        const int r0 = (tid >> 4) * 8, c0 = (tid & 15) * 4;
        ull a0[8][2];
        ulonglong2 bb = *(const ulonglong2*)&bs1[c0];
#pragma unroll
        for (int u = 0; u < 8; u++) { a0[u][0] = bb.x; a0[u][1] = bb.y; }
#pragma unroll 8
        for (int d = 0; d < 64; d++) {
            ulonglong2 wv = *(const ulonglong2*)&W1s[d * 64 + c0];
#pragma unroll
            for (int u = 0; u < 8; u++) {
                ull ad = dup2(xi[(r0 + u) * 64 + d]);
                fma2(a0[u][0], ad, wv.x);
                fma2(a0[u][1], ad, wv.y);
            }
        }
#pragma unroll
        for (int u = 0; u < 8; u++) {
            float2 p0 = unpk(a0[u][0]), p1 = unpk(a0[u][1]);
            u32 h0, l0, h1, l1;
            split2(p0.x, p0.y, h0, l0);
            split2(p1.x, p1.y, h1, l1);
            u32 off = (u32)(r0 + u) * 144 + (u32)c0 * 2;
            *(uint2*)(SB + E1H + off) = make_uint2(h0, h1);
            *(uint2*)(SB + E1L + off) = make_uint2(l0, l1);
        }
    }
    __syncthreads();

    cp_tile(sb + E2B, g_e2h + tb * 8192, tid);
    cp_tile(sb + E2B + 9216, g_e2l + tb * 8192, tid);
    cp_commit();
    cp_tile(sb + E2B + 18432, g_e2h + (tb + 1) * 8192, tid);
    cp_tile(sb + E2B + 18432 + 9216, g_e2l + (tb + 1) * 8192, tid);
    cp_commit();

    // ---- resident E1 A-fragments (rows w*16..w*16+15) ----
    u32 ah[4][4], al[4][4];
    {
        u32 arow = (u32)(w * 16 + (l & 7) + ((l >> 3) & 1) * 8);
        u32 acol = ((u32)(l >> 4)) * 16;
#pragma unroll
        for (int kc = 0; kc < 4; kc++) {
            ldm4(sb + E1H + arow * 144 + kc * 32 + acol,
                 ah[kc][0], ah[kc][1], ah[kc][2], ah[kc][3]);
            ldm4(sb + E1L + arow * 144 + kc * 32 + acol,
                 al[kc][0], al[kc][1], al[kc][2], al[kc][3]);
        }
    }
    cp_wait<0>();
    __syncthreads();  // XT0,XT1,E2(0),E2(1) all resident

    const u32 brl = (u32)((l & 7) * 144 + ((l >> 3) & 1) * 16);
    const u32 bq = (u32)(l >> 4);

    float Hc[8][4];
#pragma unroll
    for (int nb = 0; nb < 8; nb++)
#pragma unroll
        for (int v = 0; v < 4; v++) Hc[nb][v] = 0.f;
    float rsg = 0.f, rsg8 = 0.f;

    float S0[8][4], S1[8][4];
    // prologue: S0 = GEMM1(0) from e2 buf0
#pragma unroll
    for (int nb = 0; nb < 8; nb++)
#pragma unroll
        for (int v = 0; v < 4; v++) S0[nb][v] = 0.f;
#pragma unroll
    for (int kc = 0; kc < 4; kc++) gemm_kc(S0, ah[kc], al[kc], sb + E2B, brl, bq, kc);

// One pipelined iteration: GEMM1(JT+1)->SN ∥ exp/split(SC) -> GEMM2(JT).
#define ITER(JT, SC, SN)                                                          \
    {                                                                             \
        const int jt_ = (JT);                                                     \
        const u32 e2n = sb + E2B + (u32)((jt_ + 1) & 1) * 18432;                  \
        const u32 xtb = sb + XTB + (u32)(jt_ & 1) * 18432;                        \
        if (jt_ < 7) {                                                            \
            _Pragma("unroll") for (int nb = 0; nb < 8; nb++)                      \
                _Pragma("unroll") for (int v = 0; v < 4; v++) SN[nb][v] = 0.f;    \
            _Pragma("unroll") for (int kc = 0; kc < 4; kc++)                      \
                gemm_kc(SN, ah[kc], al[kc], e2n, brl, bq, kc);                    \
        }                                                                         \
        u32 pah[4][4], pal[4][4];                                                 \
        _Pragma("unroll") for (int nb = 0; nb < 8; nb++) {                        \
            float p0 = __expf(fmaxf(SC[nb][0], 0.f));                             \
            float p1 = __expf(fmaxf(SC[nb][1], 0.f));                             \
            float p2 = __expf(fmaxf(SC[nb][2], 0.f));                             \
            float p3 = __expf(fmaxf(SC[nb][3], 0.f));                             \
            rsg += p0 + p1;                                                       \
            rsg8 += p2 + p3;                                                      \
            int kc = nb >> 1, hf = (nb & 1) * 2;                                  \
            split2(p0, p1, pah[kc][hf], pal[kc][hf]);                             \
            split2(p2, p3, pah[kc][hf + 1], pal[kc][hf + 1]);                     \
        }                                                                         \
        _Pragma("unroll") for (int kc = 0; kc < 4; kc++)                          \
            gemm_kc(Hc, pah[kc], pal[kc], xtb, brl, bq, kc);                      \
        __syncthreads();                                                          \
        if (jt_ + 2 < 8) {                                                        \
            u32 dE = sb + E2B + (u32)(jt_ & 1) * 18432;                           \
            u32 dX = sb + XTB + (u32)(jt_ & 1) * 18432;                           \
            cp_tile(dE, g_e2h + (tb + jt_ + 2) * 8192, tid);                      \
            cp_tile(dE + 9216, g_e2l + (tb + jt_ + 2) * 8192, tid);               \
            cp_tile(dX, g_xth + (tb + jt_ + 2) * 8192, tid);                      \
            cp_tile(dX + 9216, g_xtl + (tb + jt_ + 2) * 8192, tid);               \
            cp_commit();                                                          \
        } else if (jt_ == 6) {                                                    \
            float* Wf = (float*)(SB + XTB);                                       \
            _Pragma("unroll") for (int i = 0; i < 8; i++) {                       \
                int ch = tid + 128 * i;                                           \
                cp16(&Wf[ch * 4], &W[ch * 4]);                                    \
            }                                                                     \
            cp_commit();                                                          \
        }                                                                         \
        cp_wait<0>();                                                             \
        __syncthreads();                                                          \
    }

    for (int jt = 0; jt < 8; jt += 2) {
        ITER(jt, S0, S1);
        ITER(jt + 1, S1, S0);
    }
#undef ITER

    // ---- rowsum reduce (quad lanes share rows) ----
    rsg += __shfl_xor_sync(0xffffffffu, rsg, 1);
    rsg += __shfl_xor_sync(0xffffffffu, rsg, 2);
    rsg8 += __shfl_xor_sync(0xffffffffu, rsg8, 1);
    rsg8 += __shfl_xor_sync(0xffffffffu, rsg8, 2);
    const float ivg = 1.f / rsg, ivg8 = 1.f / rsg8;

    // ---- W^T split planes -> E2 buf0 region ----
    {
        const float* Wf = (const float*)(SB + XTB);
        int h = tid >> 1, dh = (tid & 1) * 32;
        u32 wh[16], wl[16];
#pragma unroll
        for (int c = 0; c < 16; c++) {
            float v0 = Wf[(dh + 2 * c) * 64 + h];
            float v1 = Wf[(dh + 2 * c + 1) * 64 + h];
            split2(v0, v1, wh[c], wl[c]);
        }
        u32 off = (u32)h * 144 + (u32)dh * 2;
#pragma unroll
        for (int c4 = 0; c4 < 4; c4++) {
            *(uint4*)(SB + E2B + off + 16 * c4) = *(uint4*)&wh[4 * c4];
            *(uint4*)(SB + E2B + 9216 + off + 16 * c4) = *(uint4*)&wl[4 * c4];
        }
    }
    __syncthreads();

    // ---- normalize H -> A-frags ----
    u32 hah[4][4], hal[4][4];
#pragma unroll
    for (int nb = 0; nb < 8; nb++) {
        float q0 = Hc[nb][0] * ivg, q1 = Hc[nb][1] * ivg;
        float q2 = Hc[nb][2] * ivg8, q3 = Hc[nb][3] * ivg8;
        int kc = nb >> 1, hf = (nb & 1) * 2;
        split2(q0, q1, hah[kc][hf], hal[kc][hf]);
        split2(q2, q3, hah[kc][hf + 1], hal[kc][hf + 1]);
    }

    // ---- GEMM3: O = H_n W + b ----
    const float* bsO = (const float*)(SB + BSO);
    const int tq = l & 3, g = l >> 2;
    float O[8][4];
#pragma unroll
    for (int nb = 0; nb < 8; nb++) {
        float b0 = bsO[nb * 8 + 2 * tq], b1f = bsO[nb * 8 + 2 * tq + 1];
        O[nb][0] = b0; O[nb][1] = b1f; O[nb][2] = b0; O[nb][3] = b1f;
    }
#pragma unroll
    for (int kc = 0; kc < 4; kc++) gemm_kc(O, hah[kc], hal[kc], sb + E2B, brl, bq, kc);

    // ---- store (D-frag rows g, g+8) ----
    {
        int rg = i0 + w * 16 + g;
        float* o0 = out + ((size_t)(b * Nn + rg) * Tt + t) * Hh;
        float* o1 = o0 + (size_t)8 * Tt * Hh;
#pragma unroll
        for (int nb = 0; nb < 8; nb++) {
            int col = nb * 8 + 2 * tq;
            float2 v0 = make_float2(fmaxf(O[nb][0], 0.f), fmaxf(O[nb][1], 0.f));
            float2 v1 = make_float2(fmaxf(O[nb][2], 0.f), fmaxf(O[nb][3], 0.f));
            *(float2*)&o0[col] = v0;
            *(float2*)&o1[col] = v1;
        }
    }
}

// ============================================================================
extern "C" void kernel_launch(void* const* d_in, const int* in_sizes, int n_in,
                              void* d_out, int out_size) {
    const float* x  = (const float*)d_in[0];
    const float* W1 = (const float*)d_in[1];
    const float* b1 = (const float*)d_in[2];
    const float* W2 = (const float*)d_in[3];
    const float* b2 = (const float*)d_in[4];
    const float* W  = (const float*)d_in[5];
    const float* bias = (const float*)d_in[6];
    float* out = (float*)d_out;

    const int smemP = 8512 * 4;   // 34,048 B
    const int smemM = 92672;      // bytes
    cudaFuncSetAttribute(gcn_proj, cudaFuncAttributeMaxDynamicSharedMemorySize, smemP);
    cudaFuncSetAttribute(gcn_main, cudaFuncAttributeMaxDynamicSharedMemorySize, smemM);

    gcn_proj<<<Bb * Tt * 8, 128, smemP>>>(x, W2, b2);
    gcn_main<<<Bb * Tt * 8, 128, smemM>>>(x, W1, b1, W, bias, out);
}

// round 15
// speedup vs baseline: 1.1702x; 1.1702x over previous
#include <cuda_runtime.h>
#include <cstdint>

#define Bb 16
#define Nn 512
#define Tt 24
#define Dd 64
#define Ee 64
#define Hh 64

typedef unsigned long long ull;
typedef unsigned int u32;

// bf16 hi/lo operand planes, row-major 64x64 tiles (128B rows): [(b*Tt+t)*8 + jt]
__device__ __align__(128) unsigned char g_e2h[(size_t)Bb * Tt * Nn * 128];
__device__ __align__(128) unsigned char g_e2l[(size_t)Bb * Tt * Nn * 128];
__device__ __align__(128) unsigned char g_xth[(size_t)Bb * Tt * Dd * 1024];
__device__ __align__(128) unsigned char g_xtl[(size_t)Bb * Tt * Dd * 1024];

// ---------- SIMT helpers ----------
__device__ __forceinline__ ull dup2(float a) {
    ull r; asm("mov.b64 %0, {%1, %1};" : "=l"(r) : "f"(a)); return r;
}
__device__ __forceinline__ void fma2(ull& c, ull a, ull b) {
    asm("fma.rn.f32x2 %0, %1, %2, %0;" : "+l"(c) : "l"(a), "l"(b));
}
__device__ __forceinline__ float2 unpk(ull v) {
    float2 r; asm("mov.b64 {%0, %1}, %2;" : "=f"(r.x), "=f"(r.y) : "l"(v)); return r;
}
__device__ __forceinline__ void cp16(void* s, const void* g) {
    u32 sa = (u32)__cvta_generic_to_shared(s);
    asm volatile("cp.async.cg.shared.global [%0], [%1], 16;" ::"r"(sa), "l"(g));
}
__device__ __forceinline__ void cp16s(u32 sa, const void* g) {
    asm volatile("cp.async.cg.shared.global [%0], [%1], 16;" ::"r"(sa), "l"(g));
}
__device__ __forceinline__ void cp_commit() { asm volatile("cp.async.commit_group;"); }
template <int N> __device__ __forceinline__ void cp_wait() {
    asm volatile("cp.async.wait_group %0;" ::"n"(N));
}
// split (v0,v1) -> bf16x2 hi (v0 in low half) + bf16x2 lo residual
__device__ __forceinline__ void split2(float v0, float v1, u32& h, u32& l) {
    u32 hp;
    asm("cvt.rn.satfinite.bf16x2.f32 %0, %1, %2;" : "=r"(hp) : "f"(v1), "f"(v0));
    float h0 = __uint_as_float(hp << 16);
    float h1 = __uint_as_float(hp & 0xffff0000u);
    float l0 = v0 - h0, l1 = v1 - h1;
    asm("cvt.rn.satfinite.bf16x2.f32 %0, %1, %2;" : "=r"(l) : "f"(l1), "f"(l0));
    h = hp;
}

// ---------- tensor-core (warp mma) helpers ----------
__device__ __forceinline__ void ldm4(u32 addr, u32& r0, u32& r1, u32& r2, u32& r3) {
    asm volatile("ldmatrix.sync.aligned.m8n8.x4.shared.b16 {%0,%1,%2,%3}, [%4];"
                 : "=r"(r0), "=r"(r1), "=r"(r2), "=r"(r3) : "r"(addr));
}
__device__ __forceinline__ void mmab(float* d, const u32* a, u32 b0, u32 b1) {
    asm volatile(
        "mma.sync.aligned.m16n8k16.row.col.f32.bf16.bf16.f32 "
        "{%0,%1,%2,%3},{%4,%5,%6,%7},{%8,%9},{%0,%1,%2,%3};"
        : "+f"(d[0]), "+f"(d[1]), "+f"(d[2]), "+f"(d[3])
        : "r"(a[0]), "r"(a[1]), "r"(a[2]), "r"(a[3]), "r"(b0), "r"(b1));
}
// copy 8KB gmem plane (64 rows x 128B) into smem rows of stride 144B
__device__ __forceinline__ void cp_tile(u32 dst, const unsigned char* src, int tid) {
#pragma unroll
    for (int i = 0; i < 4; i++) {
        int ch = tid + 128 * i;  // 0..511
        u32 row = (u32)(ch >> 3), c16 = (u32)(ch & 7);
        cp16s(dst + row * 144 + c16 * 16, src + (size_t)ch * 16);
    }
}

// One K-chunk (k=16) of a 3-term split GEMM over 8 accumulators.
__device__ __forceinline__ void gemm_kc(float (*D)[4], const u32* Ah, const u32* Al,
                                        u32 bbase, u32 brl, u32 bq, int kc) {
    u32 Bh[4][4], Bl[4][4];
#pragma unroll
    for (int nbp = 0; nbp < 4; nbp++) {
        u32 ro = ((u32)(2 * nbp) + bq) * 1152 + brl + (u32)kc * 32;
        ldm4(bbase + ro, Bh[nbp][0], Bh[nbp][1], Bh[nbp][2], Bh[nbp][3]);
        ldm4(bbase + 9216 + ro, Bl[nbp][0], Bl[nbp][1], Bl[nbp][2], Bl[nbp][3]);
    }
#pragma unroll
    for (int nbp = 0; nbp < 4; nbp++) {
        mmab(D[2 * nbp], Ah, Bh[nbp][0], Bh[nbp][1]);
        mmab(D[2 * nbp + 1], Ah, Bh[nbp][2], Bh[nbp][3]);
    }
#pragma unroll
    for (int nbp = 0; nbp < 4; nbp++) {
        mmab(D[2 * nbp], Al, Bh[nbp][0], Bh[nbp][1]);
        mmab(D[2 * nbp + 1], Al, Bh[nbp][2], Bh[nbp][3]);
    }
#pragma unroll
    for (int nbp = 0; nbp < 4; nbp++) {
        mmab(D[2 * nbp], Ah, Bl[nbp][0], Bl[nbp][1]);
        mmab(D[2 * nbp + 1], Ah, Bl[nbp][2], Bl[nbp][3]);
    }
}

// ============================================================================
// Kernel P: E2 = x@W2+b2 -> bf16 hi/lo tiles [j][e]; X^T tiles [d][j] hi/lo.
// grid = B*T*8 (j-tile 64), 128 threads.
// ============================================================================
__global__ void __launch_bounds__(128, 4)
gcn_proj(const float* __restrict__ x, const float* __restrict__ W2,
         const float* __restrict__ b2) {
    extern __shared__ float sm[];
    float* xb = sm;          // [64][68]
    float* Ws = sm + 4352;   // [64][64]
    float* bs = sm + 8448;   // 64

    const int tid = threadIdx.x;
    const int blk = blockIdx.x;
    const int nt = blk & 7, bt = blk >> 3;
    const int t = bt % Tt, b = bt / Tt;
    const int n0 = nt * 64;
    const float* xg = x + ((size_t)(b * Nn + n0) * Tt + t) * Dd;
    const size_t tile = (size_t)(b * Tt + t) * 8 + nt;

#pragma unroll
    for (int i = 0; i < 8; i++) {
        int ch = tid + 128 * i, row = ch >> 4, c16 = ch & 15;
        cp16(&xb[row * 68 + c16 * 4], &xg[(size_t)row * (Tt * Dd) + c16 * 4]);
        cp16(&Ws[ch * 4], &W2[ch * 4]);
    }
    if (tid < 16) cp16(&bs[tid * 4], &b2[tid * 4]);
    cp_commit();
    cp_wait<0>();
    __syncthreads();

    const int r0 = (tid >> 4) * 8, c0 = (tid & 15) * 4;
    ull acc[8][2];
    {
        ulonglong2 bb = *(const ulonglong2*)&bs[c0];
#pragma unroll
        for (int u = 0; u < 8; u++) { acc[u][0] = bb.x; acc[u][1] = bb.y; }
    }
#pragma unroll 8
    for (int d = 0; d < 64; d++) {
        ulonglong2 wv = *(const ulonglong2*)&Ws[d * 64 + c0];
#pragma unroll
        for (int u = 0; u < 8; u++) {
            ull ad = dup2(xb[(r0 + u) * 68 + d]);
            fma2(acc[u][0], ad, wv.x);
            fma2(acc[u][1], ad, wv.y);
        }
    }
    unsigned char* e2h = g_e2h + tile * 8192;
    unsigned char* e2l = g_e2l + tile * 8192;
#pragma unroll
    for (int u = 0; u < 8; u++) {
        float2 p0 = unpk(acc[u][0]), p1 = unpk(acc[u][1]);
        u32 h0, l0, h1, l1;
        split2(p0.x, p0.y, h0, l0);
        split2(p1.x, p1.y, h1, l1);
        u32 off = (u32)(r0 + u) * 128 + (u32)c0 * 2;
        *(uint2*)(e2h + off) = make_uint2(h0, h1);
        *(uint2*)(e2l + off) = make_uint2(l0, l1);
    }
    {
        const int dd = tid >> 1, jh = (tid & 1) * 32;
        u32 hi[16], lo[16];
#pragma unroll
        for (int c = 0; c < 16; c++) {
            float v0 = xb[(jh + 2 * c) * 68 + dd];
            float v1 = xb[(jh + 2 * c + 1) * 68 + dd];
            split2(v0, v1, hi[c], lo[c]);
        }
        unsigned char* xth = g_xth + tile * 8192;
        unsigned char* xtl = g_xtl + tile * 8192;
        u32 base = (u32)dd * 128 + (u32)jh * 2;
#pragma unroll
        for (int c4 = 0; c4 < 4; c4++) {
            *(uint4*)(xth + base + 16 * c4) = *(uint4*)&hi[4 * c4];
            *(uint4*)(xtl + base + 16 * c4) = *(uint4*)&lo[4 * c4];
        }
    }
}

// ============================================================================
// Kernel M: mma.sync main (R12 loop), single XT buffer -> 3 CTAs/SM.
// smem: E1H 0, E1L 9216, E2 double 18432 (+q*18432), XT 55296,
//       BS1 73728, BSO 73984. total 74240 bytes.
// ============================================================================
__global__ void __launch_bounds__(128, 3)
gcn_main(const float* __restrict__ x, const float* __restrict__ W1,
         const float* __restrict__ b1, const float* __restrict__ W,
         const float* __restrict__ bias, float* __restrict__ out) {
    extern __shared__ unsigned char SB[];
    const u32 sb = (u32)__cvta_generic_to_shared(SB);
    const u32 E1H = 0, E1L = 9216, E2B = 18432, XTB = 55296;
    const u32 BS1 = 73728, BSO = 73984;

    const int tid = threadIdx.x, w = tid >> 5, l = tid & 31;
    const int blk = blockIdx.x;
    const int it = blk & 7, bt = blk >> 3;
    const int t = bt % Tt, b = bt / Tt;
    const int i0 = it * 64;
    const size_t tb = (size_t)(b * Tt + t) * 8;
    const float* xg = x + ((size_t)b * Nn * Tt + t) * Dd;

    // ---- g0: x_i fp32 -> E2 buf0, W1 fp32 -> E2 buf1, biases ----
    {
        float* xi = (float*)(SB + E2B);
        float* W1s = (float*)(SB + E2B + 18432);
#pragma unroll
        for (int i = 0; i < 8; i++) {
            int ch = tid + 128 * i, row = ch >> 4, c16 = ch & 15;
            cp16(&xi[row * 64 + c16 * 4], &xg[(size_t)(i0 + row) * (Tt * Dd) + c16 * 4]);
            cp16(&W1s[ch * 4], &W1[ch * 4]);
        }
        if (tid < 16) cp16((float*)(SB + BS1) + tid * 4, b1 + tid * 4);
        else if (tid < 32) cp16((float*)(SB + BSO) + (tid - 16) * 4, bias + (tid - 16) * 4);
        cp_commit();
    }
    // g1: XT(0)
    cp_tile(sb + XTB, g_xth + tb * 8192, tid);
    cp_tile(sb + XTB + 9216, g_xtl + tb * 8192, tid);
    cp_commit();
    cp_wait<1>();  // g0 done
    __syncthreads();

    // ---- GEMM0 (SIMT): E1 = x_i @ W1 + b1 -> bf16 planes stride 144 ----
    {
        const float* xi = (const float*)(SB + E2B);
        const float* W1s = (const float*)(SB + E2B + 18432);
        const float* bs1 = (const float*)(SB + BS1);
        const int r0 = (tid >> 4) * 8, c0 = (tid & 15) * 4;
        ull a0[8][2];
        ulonglong2 bb = *(const ulonglong2*)&bs1[c0];
#pragma unroll
        for (int u = 0; u < 8; u++) { a0[u][0] = bb.x; a0[u][1] = bb.y; }
#pragma unroll 8
        for (int d = 0; d < 64; d++) {
            ulonglong2 wv = *(const ulonglong2*)&W1s[d * 64 + c0];
#pragma unroll
            for (int u = 0; u < 8; u++) {
                ull ad = dup2(xi[(r0 + u) * 64 + d]);
                fma2(a0[u][0], ad, wv.x);
                fma2(a0[u][1], ad, wv.y);
            }
        }
#pragma unroll
        for (int u = 0; u < 8; u++) {
            float2 p0 = unpk(a0[u][0]), p1 = unpk(a0[u][1]);
            u32 h0, l0, h1, l1;
            split2(p0.x, p0.y, h0, l0);
            split2(p1.x, p1.y, h1, l1);
            u32 off = (u32)(r0 + u) * 144 + (u32)c0 * 2;
            *(uint2*)(SB + E1H + off) = make_uint2(h0, h1);
            *(uint2*)(SB + E1L + off) = make_uint2(l0, l1);
        }
    }
    __syncthreads();  // staging reads done; E1 visible

    // g2: E2(0) -> buf0, g3: E2(1) -> buf1
    cp_tile(sb + E2B, g_e2h + tb * 8192, tid);
    cp_tile(sb + E2B + 9216, g_e2l + tb * 8192, tid);
    cp_commit();
    cp_tile(sb + E2B + 18432, g_e2h + (tb + 1) * 8192, tid);
    cp_tile(sb + E2B + 18432 + 9216, g_e2l + (tb + 1) * 8192, tid);
    cp_commit();

    // ---- resident E1 A-fragments (rows w*16..w*16+15) ----
    u32 ah[4][4], al[4][4];
    {
        u32 arow = (u32)(w * 16 + (l & 7) + ((l >> 3) & 1) * 8);
        u32 acol = ((u32)(l >> 4)) * 16;
#pragma unroll
        for (int kc = 0; kc < 4; kc++) {
            ldm4(sb + E1H + arow * 144 + kc * 32 + acol,
                 ah[kc][0], ah[kc][1], ah[kc][2], ah[kc][3]);
            ldm4(sb + E1L + arow * 144 + kc * 32 + acol,
                 al[kc][0], al[kc][1], al[kc][2], al[kc][3]);
        }
    }
    cp_wait<0>();
    __syncthreads();  // XT(0), E2(0), E2(1) resident

    const u32 brl = (u32)((l & 7) * 144 + ((l >> 3) & 1) * 16);
    const u32 bq = (u32)(l >> 4);

    float Hc[8][4];
#pragma unroll
    for (int nb = 0; nb < 8; nb++)
#pragma unroll
        for (int v = 0; v < 4; v++) Hc[nb][v] = 0.f;
    float rsg = 0.f, rsg8 = 0.f;

    for (int jt = 0; jt < 8; jt++) {
        const u32 e2b = sb + E2B + (u32)(jt & 1) * 18432;

        // ---- GEMM1: S = E1 E2^T ----
        float S[8][4];
#pragma unroll
        for (int nb = 0; nb < 8; nb++)
#pragma unroll
            for (int v = 0; v < 4; v++) S[nb][v] = 0.f;
#pragma unroll
        for (int kc = 0; kc < 4; kc++) gemm_kc(S, ah[kc], al[kc], e2b, brl, bq, kc);

        // ---- exp(relu), rowsums, split -> P A-frags ----
        u32 pah[4][4], pal[4][4];
#pragma unroll
        for (int nb = 0; nb < 8; nb++) {
            float p0 = __expf(fmaxf(S[nb][0], 0.f)), p1 = __expf(fmaxf(S[nb][1], 0.f));
            float p2 = __expf(fmaxf(S[nb][2], 0.f)), p3 = __expf(fmaxf(S[nb][3], 0.f));
            rsg += p0 + p1;
            rsg8 += p2 + p3;
            int kc = nb >> 1, hf = (nb & 1) * 2;
            split2(p0, p1, pah[kc][hf], pal[kc][hf]);
            split2(p2, p3, pah[kc][hf + 1], pal[kc][hf + 1]);
        }
        // XT(jt) (+ E2(jt+1) from prior iteration) must be resident
        cp_wait<0>();
        __syncthreads();

        // ---- GEMM2: H += P X ----
#pragma unroll
        for (int kc = 0; kc < 4; kc++) gemm_kc(Hc, pah[kc], pal[kc], sb + XTB, brl, bq, kc);
        __syncthreads();  // XT + e2b reads done -> buffers reusable

        bool issued = false;
        if (jt + 2 < 8) {  // E2(jt+2) into the buffer GEMM1 just read
            cp_tile(e2b, g_e2h + (tb + jt + 2) * 8192, tid);
            cp_tile(e2b + 9216, g_e2l + (tb + jt + 2) * 8192, tid);
            issued = true;
        }
        if (jt + 1 < 8) {  // XT(jt+1) into the single XT buffer
            cp_tile(sb + XTB, g_xth + (tb + jt + 1) * 8192, tid);
            cp_tile(sb + XTB + 9216, g_xtl + (tb + jt + 1) * 8192, tid);
            issued = true;
        }
        if (jt == 6) {     // W fp32 into E2 buf0 (free: GEMM1(7) reads buf1)
            float* Wf = (float*)(SB + E2B);
#pragma unroll
            for (int i = 0; i < 8; i++) { int ch = tid + 128 * i; cp16(&Wf[ch * 4], &W[ch * 4]); }
            issued = true;
        }
        if (issued) cp_commit();
    }
    cp_wait<0>();
    __syncthreads();  // W fp32 resident in E2 buf0

    // ---- rowsum reduce (quad lanes share rows) ----
    rsg += __shfl_xor_sync(0xffffffffu, rsg, 1);
    rsg += __shfl_xor_sync(0xffffffffu, rsg, 2);
    rsg8 += __shfl_xor_sync(0xffffffffu, rsg8, 1);
    rsg8 += __shfl_xor_sync(0xffffffffu, rsg8, 2);
    const float ivg = 1.f / rsg, ivg8 = 1.f / rsg8;

    // ---- W^T split planes -> XT buffer region ----
    {
        const float* Wf = (const float*)(SB + E2B);
        int h = tid >> 1, dh = (tid & 1) * 32;
        u32 wh[16], wl[16];
#pragma unroll
        for (int c = 0; c < 16; c++) {
            float v0 = Wf[(dh + 2 * c) * 64 + h];
            float v1 = Wf[(dh + 2 * c + 1) * 64 + h];
            split2(v0, v1, wh[c], wl[c]);
        }
        u32 off = (u32)h * 144 + (u32)dh * 2;
#pragma unroll
        for (int c4 = 0; c4 < 4; c4++) {
            *(uint4*)(SB + XTB + off + 16 * c4) = *(uint4*)&wh[4 * c4];
            *(uint4*)(SB + XTB + 9216 + off + 16 * c4) = *(uint4*)&wl[4 * c4];
        }
    }
    __syncthreads();

    // ---- normalize H -> A-frags ----
    u32 hah[4][4], hal[4][4];
#pragma unroll
    for (int nb = 0; nb < 8; nb++) {
        float q0 = Hc[nb][0] * ivg, q1 = Hc[nb][1] * ivg;
        float q2 = Hc[nb][2] * ivg8, q3 = Hc[nb][3] * ivg8;
        int kc = nb >> 1, hf = (nb & 1) * 2;
        split2(q0, q1, hah[kc][hf], hal[kc][hf]);
        split2(q2, q3, hah[kc][hf + 1], hal[kc][hf + 1]);
    }

    // ---- GEMM3: O = H_n W + b ----
    const float* bsO = (const float*)(SB + BSO);
    const int tq = l & 3, g = l >> 2;
    float O[8][4];
#pragma unroll
    for (int nb = 0; nb < 8; nb++) {
        float b0 = bsO[nb * 8 + 2 * tq], b1f = bsO[nb * 8 + 2 * tq + 1];
        O[nb][0] = b0; O[nb][1] = b1f; O[nb][2] = b0; O[nb][3] = b1f;
    }
#pragma unroll
    for (int kc = 0; kc < 4; kc++) gemm_kc(O, hah[kc], hal[kc], sb + XTB, brl, bq, kc);

    // ---- store (D-frag rows g, g+8) ----
    {
        int rg = i0 + w * 16 + g;
        float* o0 = out + ((size_t)(b * Nn + rg) * Tt + t) * Hh;
        float* o1 = o0 + (size_t)8 * Tt * Hh;
#pragma unroll
        for (int nb = 0; nb < 8; nb++) {
            int col = nb * 8 + 2 * tq;
            float2 v0 = make_float2(fmaxf(O[nb][0], 0.f), fmaxf(O[nb][1], 0.f));
            float2 v1 = make_float2(fmaxf(O[nb][2], 0.f), fmaxf(O[nb][3], 0.f));
            *(float2*)&o0[col] = v0;
            *(float2*)&o1[col] = v1;
        }
    }
}

// ============================================================================
extern "C" void kernel_launch(void* const* d_in, const int* in_sizes, int n_in,
                              void* d_out, int out_size) {
    const float* x  = (const float*)d_in[0];
    const float* W1 = (const float*)d_in[1];
    const float* b1 = (const float*)d_in[2];
    const float* W2 = (const float*)d_in[3];
    const float* b2 = (const float*)d_in[4];
    const float* W  = (const float*)d_in[5];
    const float* bias = (const float*)d_in[6];
    float* out = (float*)d_out;

    const int smemP = 8512 * 4;   // 34,048 B
    const int smemM = 74240;      // bytes -> 3 CTAs/SM
    cudaFuncSetAttribute(gcn_proj, cudaFuncAttributeMaxDynamicSharedMemorySize, smemP);
    cudaFuncSetAttribute(gcn_main, cudaFuncAttributeMaxDynamicSharedMemorySize, smemM);

    gcn_proj<<<Bb * Tt * 8, 128, smemP>>>(x, W2, b2);
    gcn_main<<<Bb * Tt * 8, 128, smemM>>>(x, W1, b1, W, bias, out);
}